// round 8
// baseline (speedup 1.0000x reference)
#include <cuda_runtime.h>

#define FULL 0xffffffffu

// LISTA v4: near-shuffle-free. Warp = one batch column.
// lane = h*16 + c*8 + i (h = j-half of dot, c = re/im, i = position).
// Cross-lane traffic via warp-private SHARED buffers (STS/__syncwarp/LDS)
// instead of SHFL (measured ~15-20 cyc serialized cost each on this chip).
// Only 1 shfl_xor per stage remains (h-half reduce).
// All loop operands from shared via precomputed pointers + imm offsets.
// 16 blocks x 128 threads = 64 warps = 64 columns, 1 warp/SMSP.

__global__ void __launch_bounds__(128, 1) lista_kernel(
    const float* __restrict__ y_real, const float* __restrict__ y_imag,
    const float* __restrict__ w1_real, const float* __restrict__ w1_imag,
    const float* __restrict__ w2_real, const float* __restrict__ w2_imag,
    const float* __restrict__ thr,
    const float* __restrict__ c1w, const float* __restrict__ c1b,
    const float* __restrict__ c2w, const float* __restrict__ c2b,
    float* __restrict__ out)
{
    __shared__ __align__(16) float s_w2r [1024];   // w2_real, 16 stages
    __shared__ __align__(16) float s_w2ip[1024];   // +w2_imag (c=1 table)
    __shared__ __align__(16) float s_w2in[1024];   // -w2_imag (c=0 table)
    // conv params packed per stage (32 floats):
    // [0..8]=k1, [9..11]=b1, [12..20]=k2, [21]=c2b, [22]=thr, rest pad
    __shared__ __align__(16) float s_cv[16 * 32];
    __shared__ __align__(16) float s_x[4][16];     // [warp][c*8+i]
    __shared__ __align__(16) float s_z[4][2][16];  // [warp][c][2+i], 0-padded

    const int tid  = threadIdx.x;          // 0..127
    const int w    = tid >> 5;             // warp in block
    const int lane = tid & 31;
    const int i    = lane & 7;
    const int c    = (lane >> 3) & 1;
    const int h    = lane >> 4;
    const int b    = (int)blockIdx.x * 4 + w;     // batch column

    // ---- staging: W2 tables (+/- imag), conv params, z padding ----
    {
        const float4* gr = (const float4*)w2_real;
        const float4* gi = (const float4*)w2_imag;
        #pragma unroll
        for (int k = tid; k < 256; k += 128) {
            float4 vr = gr[k];
            float4 vi = gi[k];
            ((float4*)s_w2r )[k] = vr;
            ((float4*)s_w2ip)[k] = vi;
            ((float4*)s_w2in)[k] = make_float4(-vi.x, -vi.y, -vi.z, -vi.w);
        }
    }
    #pragma unroll
    for (int k = tid; k < 512; k += 128) {
        int s = k >> 5, r = k & 31;
        float v = 0.f;
        if (r < 9)       v = c1w[s * 9 + r];
        else if (r < 12) v = c1b[s * 3 + (r - 9)];
        else if (r < 21) v = c2w[s * 9 + (r - 12)];
        else if (r == 21) v = c2b[s];
        else if (r == 22) v = thr[s];
        s_cv[k] = v;
    }
    ((float*)s_z)[tid] = 0.f;   // 128 slots: zero all (pads stay zero)

    // ---- y half-slices (own comp + sign-folded opposite) ----
    const float sgn = c ? 1.f : -1.f;
    float yc[4], yos[4];
    {
        const float* yc_ptr = c ? y_imag : y_real;
        const float* yo_ptr = c ? y_real : y_imag;
        #pragma unroll
        for (int j4 = 0; j4 < 4; j4++) {
            int j = h * 4 + j4;
            yc[j4]  = yc_ptr[j * 64 + b];
            yos[j4] = sgn * yo_ptr[j * 64 + b];
        }
    }

    // ---- precompute 16 stage HALF-biases (W1[s] y), this j-half ----
    float bias[16];
    #pragma unroll
    for (int s = 0; s < 16; s++) {
        const float4 wr = *(const float4*)(w1_real + s * 64 + i * 8 + h * 4);
        const float4 wi = *(const float4*)(w1_imag + s * 64 + i * 8 + h * 4);
        float a0 = 0.f, a1 = 0.f;
        a0 = fmaf(wr.x, yc[0], a0); a1 = fmaf(wi.x, yos[0], a1);
        a0 = fmaf(wr.y, yc[1], a0); a1 = fmaf(wi.y, yos[1], a1);
        a0 = fmaf(wr.z, yc[2], a0); a1 = fmaf(wi.z, yos[2], a1);
        a0 = fmaf(wr.w, yc[3], a0); a1 = fmaf(wi.w, yos[3], a1);
        bias[s] = a0 + a1;
    }

    __syncthreads();

    // ---- precomputed pointers (loop body = LDS [ptr + imm] only) ----
    float*       px_w = &s_x[w][c * 8 + i];                 // store (h==0)
    const float* pxc  = &s_x[w][c * 8 + h * 4];             // own comp half
    const float* pxo  = &s_x[w][(c ^ 1) * 8 + h * 4];       // opp comp half
    float*       pz_w = &s_z[w][c][2 + i];                  // store (h==0)
    const float* pzv  = &s_z[w][c][0];                      // neighbor reads
    const float* pw_r = s_w2r + i * 8 + h * 4;
    const float* pw_i = (c ? s_w2ip : s_w2in) + i * 8 + h * 4;
    const bool   e0 = (i > 0), e2 = (i < 7);                // conv2 edges

    // ---- init: x = soft(full bias[0], thr[0]) ----
    float x;
    {
        const float b0 = bias[0] + __shfl_xor_sync(FULL, bias[0], 16);
        const float t0 = s_cv[22];
        x = b0 - fminf(fmaxf(b0, -t0), t0);
    }

    // ---- 16 sequential stages ----
    #pragma unroll
    for (int s = 0; s < 16; s++) {
        // x exchange via shared (replaces 16-shfl broadcast)
        if (h == 0) *px_w = x;
        __syncwarp();
        const float4 xcv = *(const float4*)pxc;
        const float4 xov = *(const float4*)pxo;

        // half dot (weights: shared, sign pre-folded)
        const float4 wr = *(const float4*)(pw_r + s * 64);
        const float4 wi = *(const float4*)(pw_i + s * 64);
        float a0 = bias[s], a1 = 0.f;
        a0 = fmaf(wr.x, xcv.x, a0); a1 = fmaf(wi.x, xov.x, a1);
        a0 = fmaf(wr.y, xcv.y, a0); a1 = fmaf(wi.y, xov.y, a1);
        a0 = fmaf(wr.z, xcv.z, a0); a1 = fmaf(wi.z, xov.z, a1);
        a0 = fmaf(wr.w, xcv.w, a0); a1 = fmaf(wi.w, xov.w, a1);
        const float a = a0 + a1;
        const float z = a + __shfl_xor_sync(FULL, a, 16);  // h-half reduce

        // z exchange via shared (replaces 4-shfl neighbor wave; padding
        // slots are permanently zero -> no edge selects on z)
        if (h == 0) *pz_w = z;
        __syncwarp();
        float zw[5];
        zw[0] = pzv[i];         // z[i-2]
        zw[1] = pzv[i + 1];     // z[i-1]
        zw[2] = z;
        zw[3] = pzv[i + 3];     // z[i+1]
        zw[4] = pzv[i + 4];     // z[i+2]

        // conv params: 6 broadcast LDS.128
        const float4 q0 = *(const float4*)(s_cv + s * 32);
        const float4 q1 = *(const float4*)(s_cv + s * 32 + 4);
        const float4 q2 = *(const float4*)(s_cv + s * 32 + 8);
        const float4 q3 = *(const float4*)(s_cv + s * 32 + 12);
        const float4 q4 = *(const float4*)(s_cv + s * 32 + 16);
        const float4 q5 = *(const float4*)(s_cv + s * 32 + 20);
        const float k1[3][3] = {{q0.x, q0.y, q0.z},
                                {q0.w, q1.x, q1.y},
                                {q1.z, q1.w, q2.x}};
        const float bb1[3] = {q2.y, q2.z, q2.w};
        // conv2 weights with edge taps zeroed off-chain
        const float k2[3][3] = {{e0 ? q3.x : 0.f, q3.w, e2 ? q4.z : 0.f},
                                {e0 ? q3.y : 0.f, q4.x, e2 ? q4.w : 0.f},
                                {e0 ? q3.z : 0.f, q4.y, e2 ? q5.x : 0.f}};
        // NOTE: k2 flat layout is [ch*3+p3] = q3.x..q5.x in row order:
        // (0,0)(0,1)(0,2)(1,0)(1,1)(1,2)(2,0)(2,1)(2,2)
        const float k2m[3][3] = {{e0 ? q3.x : 0.f, q3.y, e2 ? q3.z : 0.f},
                                 {e0 ? q3.w : 0.f, q4.x, e2 ? q4.y : 0.f},
                                 {e0 ? q4.z : 0.f, q4.w, e2 ? q5.x : 0.f}};
        const float cb2 = q5.y;
        const float t   = q5.z;
        const float tn  = -t;
        (void)k2;

        // conv1 + soft at pos i-1, i, i+1 locally; conv2 with 3 accumulators
        float o0 = cb2, o1 = 0.f, o2 = 0.f;
        #pragma unroll
        for (int ch = 0; ch < 3; ch++) {
            const float w0 = k1[ch][0], w1 = k1[ch][1], w2 = k1[ch][2];
            const float bb = bb1[ch];
            float v0 = bb, v1 = bb, v2 = bb;
            v0 = fmaf(w0, zw[0], v0); v1 = fmaf(w0, zw[1], v1); v2 = fmaf(w0, zw[2], v2);
            v0 = fmaf(w1, zw[1], v0); v1 = fmaf(w1, zw[2], v1); v2 = fmaf(w1, zw[3], v2);
            v0 = fmaf(w2, zw[2], v0); v1 = fmaf(w2, zw[3], v1); v2 = fmaf(w2, zw[4], v2);
            const float s0 = v0 - fminf(fmaxf(v0, tn), t);   // soft, 3 ops
            const float s1 = v1 - fminf(fmaxf(v1, tn), t);
            const float s2 = v2 - fminf(fmaxf(v2, tn), t);
            o0 = fmaf(k2m[ch][0], s0, o0);
            o1 = fmaf(k2m[ch][1], s1, o1);
            o2 = fmaf(k2m[ch][2], s2, o2);
        }
        x = (o0 + o1) + o2;
    }

    // out: x_r (8,64) then x_i (8,64)
    if (h == 0) out[c * 512 + i * 64 + b] = x;
}

extern "C" void kernel_launch(void* const* d_in, const int* in_sizes, int n_in,
                              void* d_out, int out_size) {
    (void)in_sizes; (void)n_in; (void)out_size;
    const float* y_real  = (const float*)d_in[0];
    const float* y_imag  = (const float*)d_in[1];
    const float* w1_real = (const float*)d_in[2];
    const float* w1_imag = (const float*)d_in[3];
    const float* w2_real = (const float*)d_in[4];
    const float* w2_imag = (const float*)d_in[5];
    const float* thr     = (const float*)d_in[6];
    const float* c1w     = (const float*)d_in[7];
    const float* c1b     = (const float*)d_in[8];
    const float* c2w     = (const float*)d_in[9];
    const float* c2b     = (const float*)d_in[10];
    float* out = (float*)d_out;

    lista_kernel<<<16, 128>>>(y_real, y_imag, w1_real, w1_imag,
                              w2_real, w2_imag, thr, c1w, c1b, c2w, c2b, out);
}

// round 9
// speedup vs baseline: 1.0854x; 1.0854x over previous
#include <cuda_runtime.h>

#define FULL 0xffffffffu

// LISTA v5 = R5 base (wall-best) + chain trims.
// lane = h*16 + c*8 + i (h = j-half, c = re/im, i = position); warp = column.
// Per-stage: 8 shfl (x broadcast) -> 8 FMA half-dot (weights from shared,
// sign pre-folded into tables) -> 1 shfl_xor reduce -> 4 shfl z-neighbors
// -> local conv1 at i-1,i,i+1 (3-op soft) -> conv2 (edge-zeroed weights,
// 3 accumulators). W1[s]@y half-biases precomputed into registers.
// 16 blocks x 128 threads = 64 warps = 64 columns, 1 warp/SMSP.

__global__ void __launch_bounds__(128, 1) lista_kernel(
    const float* __restrict__ y_real, const float* __restrict__ y_imag,
    const float* __restrict__ w1_real, const float* __restrict__ w1_imag,
    const float* __restrict__ w2_real, const float* __restrict__ w2_imag,
    const float* __restrict__ thr,
    const float* __restrict__ c1w, const float* __restrict__ c1b,
    const float* __restrict__ c2w, const float* __restrict__ c2b,
    float* __restrict__ out)
{
    __shared__ __align__(16) float s_w2r [1024];   // w2_real, 16 stages
    __shared__ __align__(16) float s_w2ip[1024];   // +w2_imag (c=1)
    __shared__ __align__(16) float s_w2in[1024];   // -w2_imag (c=0)
    // packed conv params, 24 floats/stage:
    // [0..8]=k1 row-major, [9..11]=b1, [12..20]=k2 row-major,
    // [21]=c2b, [22]=thr, [23]=pad
    __shared__ __align__(16) float s_cv[16 * 24];

    const int tid  = threadIdx.x;          // 0..127
    const int lane = tid & 31;
    const int i    = lane & 7;
    const int c    = (lane >> 3) & 1;
    const int h    = lane >> 4;
    const int b    = (int)blockIdx.x * 4 + (tid >> 5);   // batch column

    // ---- staging: W2 tables (+/- imag), packed conv params ----
    {
        const float4* gr = (const float4*)w2_real;
        const float4* gi = (const float4*)w2_imag;
        #pragma unroll
        for (int k = tid; k < 256; k += 128) {
            float4 vr = gr[k];
            float4 vi = gi[k];
            ((float4*)s_w2r )[k] = vr;
            ((float4*)s_w2ip)[k] = vi;
            ((float4*)s_w2in)[k] = make_float4(-vi.x, -vi.y, -vi.z, -vi.w);
        }
    }
    #pragma unroll
    for (int k = tid; k < 384; k += 128) {
        int s = k / 24, r = k - s * 24;
        float v = 0.f;
        if (r < 9)        v = c1w[s * 9 + r];
        else if (r < 12)  v = c1b[s * 3 + (r - 9)];
        else if (r < 21)  v = c2w[s * 9 + (r - 12)];
        else if (r == 21) v = c2b[s];
        else if (r == 22) v = thr[s];
        s_cv[k] = v;
    }

    // ---- y half-slices (own comp + sign-folded opposite) ----
    const float sgn = c ? 1.f : -1.f;   // z_r: -wi*x_i ; z_i: +wi*x_r
    float yc[4], yos[4];
    {
        const float* yc_ptr = c ? y_imag : y_real;
        const float* yo_ptr = c ? y_real : y_imag;
        #pragma unroll
        for (int j4 = 0; j4 < 4; j4++) {
            int j = h * 4 + j4;
            yc[j4]  = yc_ptr[j * 64 + b];
            yos[j4] = sgn * yo_ptr[j * 64 + b];
        }
    }

    // ---- precompute 16 stage HALF-biases (W1[s] y), this j-half ----
    float bias[16];
    #pragma unroll
    for (int s = 0; s < 16; s++) {
        const float4 wr = *(const float4*)(w1_real + s * 64 + i * 8 + h * 4);
        const float4 wi = *(const float4*)(w1_imag + s * 64 + i * 8 + h * 4);
        float a0 = 0.f, a1 = 0.f;
        a0 = fmaf(wr.x, yc[0], a0); a1 = fmaf(wi.x, yos[0], a1);
        a0 = fmaf(wr.y, yc[1], a0); a1 = fmaf(wi.y, yos[1], a1);
        a0 = fmaf(wr.z, yc[2], a0); a1 = fmaf(wi.z, yos[2], a1);
        a0 = fmaf(wr.w, yc[3], a0); a1 = fmaf(wi.w, yos[3], a1);
        bias[s] = a0 + a1;
    }

    __syncthreads();

    // ---- static pointers (loop body: LDS [ptr + imm] only) ----
    const float* pw_r = s_w2r + i * 8 + h * 4;
    const float* pw_i = (c ? s_w2ip : s_w2in) + i * 8 + h * 4;
    const bool   e0 = (i > 0), e2 = (i < 7);

    // ---- init: x = soft(full bias[0], thr[0]) ----
    float x;
    {
        const float b0 = bias[0] + __shfl_xor_sync(FULL, bias[0], 16);
        const float t0 = s_cv[22];
        x = b0 - fminf(fmaxf(b0, -t0), t0);
    }

    const int src_c = (c << 3);        // lanes holding own-comp x_j
    const int src_o = ((c ^ 1) << 3);  // lanes holding opposite-comp x_j
    const int nbase = lane & 24;       // keep (c,h) bits for neighbor shfl

    // ---- 16 sequential stages (fully unrolled) ----
    #pragma unroll
    for (int s = 0; s < 16; s++) {
        // broadcast x for this thread's j-half (sign folded in weights,
        // so shuffled values are used raw)
        float xc[4], xo[4];
        #pragma unroll
        for (int j4 = 0; j4 < 4; j4++) {
            int j = h * 4 + j4;
            xc[j4] = __shfl_sync(FULL, x, src_c + j);
            xo[j4] = __shfl_sync(FULL, x, src_o + j);
        }

        // half dot from shared weight tables
        const float4 wr = *(const float4*)(pw_r + s * 64);
        const float4 wi = *(const float4*)(pw_i + s * 64);
        float a0 = bias[s], a1 = 0.f;
        a0 = fmaf(wr.x, xc[0], a0); a1 = fmaf(wi.x, xo[0], a1);
        a0 = fmaf(wr.y, xc[1], a0); a1 = fmaf(wi.y, xo[1], a1);
        a0 = fmaf(wr.z, xc[2], a0); a1 = fmaf(wi.z, xo[2], a1);
        a0 = fmaf(wr.w, xc[3], a0); a1 = fmaf(wi.w, xo[3], a1);
        const float a = a0 + a1;
        const float z = a + __shfl_xor_sync(FULL, a, 16);  // full bias+dot

        // z neighbors at +-1,+-2 (same component, zero-padded via SEL)
        float zv[5];
        zv[2] = z;
        float zm2 = __shfl_sync(FULL, z, nbase | ((i - 2) & 7));
        float zm1 = __shfl_sync(FULL, z, nbase | ((i - 1) & 7));
        float zp1 = __shfl_sync(FULL, z, nbase | ((i + 1) & 7));
        float zp2 = __shfl_sync(FULL, z, nbase | ((i + 2) & 7));
        zv[0] = (i >= 2) ? zm2 : 0.f;
        zv[1] = (i >= 1) ? zm1 : 0.f;
        zv[3] = (i <= 6) ? zp1 : 0.f;
        zv[4] = (i <= 5) ? zp2 : 0.f;

        // packed conv params: 6 broadcast LDS.128
        const float4 q0 = *(const float4*)(s_cv + s * 24);
        const float4 q1 = *(const float4*)(s_cv + s * 24 + 4);
        const float4 q2 = *(const float4*)(s_cv + s * 24 + 8);
        const float4 q3 = *(const float4*)(s_cv + s * 24 + 12);
        const float4 q4 = *(const float4*)(s_cv + s * 24 + 16);
        const float4 q5 = *(const float4*)(s_cv + s * 24 + 20);
        const float k1[3][3] = {{q0.x, q0.y, q0.z},
                                {q0.w, q1.x, q1.y},
                                {q1.z, q1.w, q2.x}};
        const float bb1[3] = {q2.y, q2.z, q2.w};
        // k2 row-major with edge taps zeroed OFF the z-dependent chain
        const float k2m[3][3] = {{e0 ? q3.x : 0.f, q3.y, e2 ? q3.z : 0.f},
                                 {e0 ? q3.w : 0.f, q4.x, e2 ? q4.y : 0.f},
                                 {e0 ? q4.z : 0.f, q4.w, e2 ? q5.x : 0.f}};
        const float cb2 = q5.y;
        const float t   = q5.z;
        const float tn  = -t;

        // conv1 + 3-op soft at pos i-1, i, i+1; conv2 with 3 accumulators
        float o0 = cb2, o1 = 0.f, o2 = 0.f;
        #pragma unroll
        for (int ch = 0; ch < 3; ch++) {
            const float w0 = k1[ch][0], w1 = k1[ch][1], w2 = k1[ch][2];
            const float bb = bb1[ch];
            float v0 = bb, v1 = bb, v2 = bb;
            v0 = fmaf(w0, zv[0], v0); v1 = fmaf(w0, zv[1], v1); v2 = fmaf(w0, zv[2], v2);
            v0 = fmaf(w1, zv[1], v0); v1 = fmaf(w1, zv[2], v1); v2 = fmaf(w1, zv[3], v2);
            v0 = fmaf(w2, zv[2], v0); v1 = fmaf(w2, zv[3], v1); v2 = fmaf(w2, zv[4], v2);
            const float s0 = v0 - fminf(fmaxf(v0, tn), t);
            const float s1 = v1 - fminf(fmaxf(v1, tn), t);
            const float s2 = v2 - fminf(fmaxf(v2, tn), t);
            o0 = fmaf(k2m[ch][0], s0, o0);
            o1 = fmaf(k2m[ch][1], s1, o1);
            o2 = fmaf(k2m[ch][2], s2, o2);
        }
        x = (o0 + o1) + o2;
    }

    // out: x_r (8,64) then x_i (8,64); h=0 lanes write
    if (h == 0) out[c * 512 + i * 64 + b] = x;
}

extern "C" void kernel_launch(void* const* d_in, const int* in_sizes, int n_in,
                              void* d_out, int out_size) {
    (void)in_sizes; (void)n_in; (void)out_size;
    const float* y_real  = (const float*)d_in[0];
    const float* y_imag  = (const float*)d_in[1];
    const float* w1_real = (const float*)d_in[2];
    const float* w1_imag = (const float*)d_in[3];
    const float* w2_real = (const float*)d_in[4];
    const float* w2_imag = (const float*)d_in[5];
    const float* thr     = (const float*)d_in[6];
    const float* c1w     = (const float*)d_in[7];
    const float* c1b     = (const float*)d_in[8];
    const float* c2w     = (const float*)d_in[9];
    const float* c2b     = (const float*)d_in[10];
    float* out = (float*)d_out;

    lista_kernel<<<16, 128>>>(y_real, y_imag, w1_real, w1_imag,
                              w2_real, w2_imag, thr, c1w, c1b, c2w, c2b, out);
}